// round 1
// baseline (speedup 1.0000x reference)
#include <cuda_runtime.h>
#include <cstdint>
#include <cstddef>

typedef unsigned long long ull;

#define NNODES 50000
#define NEDGES 800000
#define DIM 64

// Scratch (device globals: no allocation allowed in kernel_launch)
__device__ float g_node_x[NNODES * DIM];   // segment-sum result
__device__ float g_y[NNODES * DIM];        // node_x @ W1
__device__ int   g_is64;                   // index dtype flag

// ---------- packed f32x2 helpers (Blackwell FFMA2 via PTX) ----------
__device__ __forceinline__ void fma2(ull& acc, ull a, ull b) {
    asm("fma.rn.f32x2 %0, %1, %2, %0;" : "+l"(acc) : "l"(a), "l"(b));
}
__device__ __forceinline__ ull pack2(float x, float y) {
    ull r; asm("mov.b64 %0, {%1, %2};" : "=l"(r) : "f"(x), "f"(y)); return r;
}
__device__ __forceinline__ float2 unpack2(ull v) {
    float2 r; asm("mov.b64 {%0, %1}, %2;" : "=f"(r.x), "=f"(r.y) : "l"(v)); return r;
}

// ---------- dtype detect: int64 indices read as int32 give zeros at odd slots ----------
__global__ void detect_kernel(const int* __restrict__ src) {
    if (threadIdx.x == 0) {
        int z = 1;
        #pragma unroll
        for (int i = 0; i < 32; i++) z &= (src[2 * i + 1] == 0);
        g_is64 = z;
    }
}

__global__ void zero_kernel() {
    int i = blockIdx.x * blockDim.x + threadIdx.x;
    float4* p = (float4*)g_node_x;
    if (i < NNODES * DIM / 4) p[i] = make_float4(0.f, 0.f, 0.f, 0.f);
}

// ---------- phase 1: node_x[dst] += edge_feat  (vectorized L2 atomics) ----------
__global__ void scatter_kernel(const float4* __restrict__ ef, const void* __restrict__ dstp) {
    int t = blockIdx.x * blockDim.x + threadIdx.x;
    if (t >= NEDGES * (DIM / 4)) return;
    int e = t >> 4;        // edge
    int q = t & 15;        // which float4 of the 64-wide row
    long long d = g_is64 ? ((const long long*)dstp)[e]
                         : (long long)((const int*)dstp)[e];
    float4 v = ef[t];
    float* addr = g_node_x + d * DIM + q * 4;
    asm volatile("red.global.add.v4.f32 [%0], {%1, %2, %3, %4};"
                 :: "l"(addr), "f"(v.x), "f"(v.y), "f"(v.z), "f"(v.w) : "memory");
}

// ---------- phase 2: y = node_x @ W1 (warp per node, W1 in regs, FFMA2) ----------
__global__ void __launch_bounds__(128, 1) node_mm_kernel(const float* __restrict__ W1) {
    __shared__ float sh[4][DIM];
    int lane = threadIdx.x & 31;
    int warp = threadIdx.x >> 5;
    int gw = blockIdx.x * 4 + warp;
    int nw = gridDim.x * 4;
    int j0 = lane * 2;

    // lane owns output cols j0, j0+1.  wA[p] = (W1[2p][j0], W1[2p+1][j0])  (k-pair packed)
    ull wA[32], wB[32];
    #pragma unroll
    for (int p = 0; p < 32; p++) {
        wA[p] = pack2(W1[(2 * p) * DIM + j0],     W1[(2 * p + 1) * DIM + j0]);
        wB[p] = pack2(W1[(2 * p) * DIM + j0 + 1], W1[(2 * p + 1) * DIM + j0 + 1]);
    }

    for (int node = gw; node < NNODES; node += nw) {
        if (lane < 16)
            ((float4*)sh[warp])[lane] = ((const float4*)(g_node_x + node * DIM))[lane];
        __syncwarp();
        ull a0 = 0, a1 = 0, c0 = 0, c1 = 0;
        const ulonglong2* hh = (const ulonglong2*)sh[warp];
        #pragma unroll
        for (int m = 0; m < 16; m += 2) {
            ulonglong2 h0 = hh[m], h1 = hh[m + 1];
            fma2(a0, h0.x, wA[2 * m]);     fma2(c0, h0.x, wB[2 * m]);
            fma2(a0, h0.y, wA[2 * m + 1]); fma2(c0, h0.y, wB[2 * m + 1]);
            fma2(a1, h1.x, wA[2 * m + 2]); fma2(c1, h1.x, wB[2 * m + 2]);
            fma2(a1, h1.y, wA[2 * m + 3]); fma2(c1, h1.y, wB[2 * m + 3]);
        }
        __syncwarp();
        float2 ra0 = unpack2(a0), ra1 = unpack2(a1);
        float2 rc0 = unpack2(c0), rc1 = unpack2(c1);
        float2 o = make_float2(ra0.x + ra0.y + ra1.x + ra1.y,
                               rc0.x + rc0.y + rc1.x + rc1.y);
        ((float2*)(g_y + node * DIM))[lane] = o;
    }
}

// ---------- phase 3: per edge: h = relu(y_s + y_d + b1); out = 0.5*(h@W2 + b2) ----------
__global__ void __launch_bounds__(128, 1) edge_kernel(
    const void* __restrict__ srcp, const void* __restrict__ dstp,
    const float* __restrict__ W2, const float* __restrict__ b1,
    const float* __restrict__ b2, float* __restrict__ out)
{
    __shared__ float sh[4][DIM];
    int lane = threadIdx.x & 31;
    int warp = threadIdx.x >> 5;
    int gw = blockIdx.x * 4 + warp;
    int nw = gridDim.x * 4;
    int j0 = lane * 2;
    int is64 = g_is64;

    ull wA[32], wB[32];
    #pragma unroll
    for (int p = 0; p < 32; p++) {
        wA[p] = pack2(W2[(2 * p) * DIM + j0],     W2[(2 * p + 1) * DIM + j0]);
        wB[p] = pack2(W2[(2 * p) * DIM + j0 + 1], W2[(2 * p + 1) * DIM + j0 + 1]);
    }
    float2 b1p = ((const float2*)b1)[lane];   // h positions 2l, 2l+1
    float2 b2p = ((const float2*)b2)[lane];   // out cols j0, j0+1

    for (int e = gw; e < NEDGES; e += nw) {
        long long s, d;
        if (is64) { s = ((const long long*)srcp)[e]; d = ((const long long*)dstp)[e]; }
        else      { s = ((const int*)srcp)[e];       d = ((const int*)dstp)[e];       }

        float2 ys = ((const float2*)(g_y + s * DIM))[lane];
        float2 yd = ((const float2*)(g_y + d * DIM))[lane];
        float2 h = make_float2(fmaxf(ys.x + yd.x + b1p.x, 0.f),
                               fmaxf(ys.y + yd.y + b1p.y, 0.f));
        ((float2*)sh[warp])[lane] = h;
        __syncwarp();

        ull a0 = 0, a1 = 0, c0 = 0, c1 = 0;
        const ulonglong2* hh = (const ulonglong2*)sh[warp];
        #pragma unroll
        for (int m = 0; m < 16; m += 2) {
            ulonglong2 h0 = hh[m], h1 = hh[m + 1];
            fma2(a0, h0.x, wA[2 * m]);     fma2(c0, h0.x, wB[2 * m]);
            fma2(a0, h0.y, wA[2 * m + 1]); fma2(c0, h0.y, wB[2 * m + 1]);
            fma2(a1, h1.x, wA[2 * m + 2]); fma2(c1, h1.x, wB[2 * m + 2]);
            fma2(a1, h1.y, wA[2 * m + 3]); fma2(c1, h1.y, wB[2 * m + 3]);
        }
        __syncwarp();

        float2 ra0 = unpack2(a0), ra1 = unpack2(a1);
        float2 rc0 = unpack2(c0), rc1 = unpack2(c1);
        float2 o = make_float2(0.5f * (ra0.x + ra0.y + ra1.x + ra1.y) + 0.5f * b2p.x,
                               0.5f * (rc0.x + rc0.y + rc1.x + rc1.y) + 0.5f * b2p.y);
        ((float2*)(out + (size_t)e * DIM))[lane] = o;
    }
}

extern "C" void kernel_launch(void* const* d_in, const int* in_sizes, int n_in,
                              void* d_out, int out_size) {
    const float4* edge_feat = (const float4*)d_in[0];
    const void*   src       = d_in[1];
    const void*   dst       = d_in[2];
    const float*  W1        = (const float*)d_in[3];
    const float*  b1        = (const float*)d_in[4];
    const float*  W2        = (const float*)d_in[5];
    const float*  b2        = (const float*)d_in[6];
    float*        out       = (float*)d_out;

    detect_kernel<<<1, 32>>>((const int*)src);
    zero_kernel<<<(NNODES * DIM / 4 + 255) / 256, 256>>>();
    scatter_kernel<<<(NEDGES * 16 + 255) / 256, 256>>>(edge_feat, dst);
    node_mm_kernel<<<1024, 128>>>(W1);
    edge_kernel<<<2048, 128>>>(src, dst, W2, b1, b2, out);
}

// round 2
// speedup vs baseline: 1.4002x; 1.4002x over previous
#include <cuda_runtime.h>
#include <cstdint>
#include <cstddef>

typedef unsigned long long ull;

#define NNODES 50000
#define NEDGES 800000
#define DIM 64

__device__ float g_node_x[NNODES * DIM];
__device__ float g_y[NNODES * DIM];        // node_x @ W1 + 0.5*b1
__device__ int   g_is64;

// ---------- packed f32x2 helpers (Blackwell FFMA2 via PTX) ----------
__device__ __forceinline__ void fma2(ull& acc, ull a, ull b) {
    asm("fma.rn.f32x2 %0, %1, %2, %0;" : "+l"(acc) : "l"(a), "l"(b));
}
__device__ __forceinline__ ull pack2(float x, float y) {
    ull r; asm("mov.b64 %0, {%1, %2};" : "=l"(r) : "f"(x), "f"(y)); return r;
}
__device__ __forceinline__ float2 unpack2(ull v) {
    float2 r; asm("mov.b64 {%0, %1}, %2;" : "=f"(r.x), "=f"(r.y) : "l"(v)); return r;
}

// ---------- int64 detect ----------
__global__ void detect_kernel(const int* __restrict__ src) {
    if (threadIdx.x == 0) {
        int z = 1;
        #pragma unroll
        for (int i = 0; i < 32; i++) z &= (src[2 * i + 1] == 0);
        g_is64 = z;
    }
}

__global__ void zero_kernel() {
    int i = blockIdx.x * blockDim.x + threadIdx.x;
    float4* p = (float4*)g_node_x;
    if (i < NNODES * DIM / 4) p[i] = make_float4(0.f, 0.f, 0.f, 0.f);
}

// ---------- phase 1: node_x[dst] += edge_feat (vectorized L2 reductions) ----------
__global__ void scatter_kernel(const float4* __restrict__ ef, const void* __restrict__ dstp) {
    int t = blockIdx.x * blockDim.x + threadIdx.x;
    if (t >= NEDGES * (DIM / 4)) return;
    int e = t >> 4;
    int q = t & 15;
    long long d = g_is64 ? ((const long long*)dstp)[e]
                         : (long long)((const int*)dstp)[e];
    float4 v = ef[t];
    float* addr = g_node_x + d * DIM + q * 4;
    asm volatile("red.global.add.v4.f32 [%0], {%1, %2, %3, %4};"
                 :: "l"(addr), "f"(v.x), "f"(v.y), "f"(v.z), "f"(v.w) : "memory");
}

// ---------- phase 2: y = node_x @ W1 + 0.5*b1 ----------
__global__ void __launch_bounds__(128, 2) node_mm_kernel(const float* __restrict__ W1,
                                                         const float* __restrict__ b1) {
    __shared__ float sh[4][DIM];
    int lane = threadIdx.x & 31;
    int warp = threadIdx.x >> 5;
    int gw = blockIdx.x * 4 + warp;
    int nw = gridDim.x * 4;
    int j0 = lane * 2;

    ull wA[32], wB[32];
    #pragma unroll
    for (int p = 0; p < 32; p++) {
        wA[p] = pack2(W1[(2 * p) * DIM + j0],     W1[(2 * p + 1) * DIM + j0]);
        wB[p] = pack2(W1[(2 * p) * DIM + j0 + 1], W1[(2 * p + 1) * DIM + j0 + 1]);
    }
    float2 b1h = make_float2(0.5f * b1[j0], 0.5f * b1[j0 + 1]);

    for (int node = gw; node < NNODES; node += nw) {
        if (lane < 16)
            ((float4*)sh[warp])[lane] = ((const float4*)(g_node_x + node * DIM))[lane];
        __syncwarp();
        ull a0 = 0, a1 = 0, c0 = 0, c1 = 0;
        const ulonglong2* hh = (const ulonglong2*)sh[warp];
        #pragma unroll
        for (int m = 0; m < 16; m += 2) {
            ulonglong2 h0 = hh[m], h1 = hh[m + 1];
            fma2(a0, h0.x, wA[2 * m]);     fma2(c0, h0.x, wB[2 * m]);
            fma2(a0, h0.y, wA[2 * m + 1]); fma2(c0, h0.y, wB[2 * m + 1]);
            fma2(a1, h1.x, wA[2 * m + 2]); fma2(c1, h1.x, wB[2 * m + 2]);
            fma2(a1, h1.y, wA[2 * m + 3]); fma2(c1, h1.y, wB[2 * m + 3]);
        }
        __syncwarp();
        float2 ra0 = unpack2(a0), ra1 = unpack2(a1);
        float2 rc0 = unpack2(c0), rc1 = unpack2(c1);
        float2 o = make_float2(ra0.x + ra0.y + ra1.x + ra1.y + b1h.x,
                               rc0.x + rc0.y + rc1.x + rc1.y + b1h.y);
        ((float2*)(g_y + node * DIM))[lane] = o;
    }
}

// ---------- phase 3: 2 edges per warp iteration, prefetched gathers ----------
__device__ __forceinline__ void load_edge(const void* __restrict__ srcp,
                                          const void* __restrict__ dstp,
                                          int is64, int e, int lane,
                                          float2& ys, float2& yd) {
    long long s, d;
    if (is64) { s = ((const long long*)srcp)[e]; d = ((const long long*)dstp)[e]; }
    else      { s = ((const int*)srcp)[e];       d = ((const int*)dstp)[e];       }
    ys = ((const float2*)(g_y + s * DIM))[lane];
    yd = ((const float2*)(g_y + d * DIM))[lane];
}

__global__ void __launch_bounds__(128, 2) edge_kernel(
    const void* __restrict__ srcp, const void* __restrict__ dstp,
    const float* __restrict__ W2, const float* __restrict__ b2,
    float* __restrict__ out)
{
    __shared__ float sh[4][2][DIM];
    int lane = threadIdx.x & 31;
    int warp = threadIdx.x >> 5;
    int gw = blockIdx.x * 4 + warp;
    int nw = gridDim.x * 4;
    int j0 = lane * 2;
    int is64 = g_is64;

    ull wA[32], wB[32];
    #pragma unroll
    for (int p = 0; p < 32; p++) {
        wA[p] = pack2(W2[(2 * p) * DIM + j0],     W2[(2 * p + 1) * DIM + j0]);
        wB[p] = pack2(W2[(2 * p) * DIM + j0 + 1], W2[(2 * p + 1) * DIM + j0 + 1]);
    }
    float2 b2p = ((const float2*)b2)[lane];
    b2p.x *= 0.5f; b2p.y *= 0.5f;

    const int NP = NEDGES / 2;
    int pi = gw;
    if (pi >= NP) return;

    float2 ys0, yd0, ys1, yd1;
    load_edge(srcp, dstp, is64, 2 * pi,     lane, ys0, yd0);
    load_edge(srcp, dstp, is64, 2 * pi + 1, lane, ys1, yd1);

    while (pi < NP) {
        float2 h0 = make_float2(fmaxf(ys0.x + yd0.x, 0.f), fmaxf(ys0.y + yd0.y, 0.f));
        float2 h1 = make_float2(fmaxf(ys1.x + yd1.x, 0.f), fmaxf(ys1.y + yd1.y, 0.f));
        ((float2*)sh[warp][0])[lane] = h0;
        ((float2*)sh[warp][1])[lane] = h1;
        __syncwarp();

        // prefetch next pair while this pair computes
        int pn = pi + nw;
        if (pn < NP) {
            load_edge(srcp, dstp, is64, 2 * pn,     lane, ys0, yd0);
            load_edge(srcp, dstp, is64, 2 * pn + 1, lane, ys1, yd1);
        }

        ull a0 = 0, a1 = 0, a2 = 0, a3 = 0, a4 = 0, a5 = 0, a6 = 0, a7 = 0;
        const ulonglong2* H0 = (const ulonglong2*)sh[warp][0];
        const ulonglong2* H1 = (const ulonglong2*)sh[warp][1];
        #pragma unroll
        for (int m = 0; m < 16; m++) {
            ulonglong2 p0 = H0[m], q0 = H1[m];
            fma2(a0, p0.x, wA[2 * m]);     fma2(a1, p0.y, wA[2 * m + 1]);
            fma2(a2, p0.x, wB[2 * m]);     fma2(a3, p0.y, wB[2 * m + 1]);
            fma2(a4, q0.x, wA[2 * m]);     fma2(a5, q0.y, wA[2 * m + 1]);
            fma2(a6, q0.x, wB[2 * m]);     fma2(a7, q0.y, wB[2 * m + 1]);
        }

        float2 r0 = unpack2(a0), r1 = unpack2(a1), r2 = unpack2(a2), r3 = unpack2(a3);
        float2 o0 = make_float2(0.5f * (r0.x + r0.y + r1.x + r1.y) + b2p.x,
                                0.5f * (r2.x + r2.y + r3.x + r3.y) + b2p.y);
        ((float2*)(out + (size_t)(2 * pi) * DIM))[lane] = o0;

        float2 r4 = unpack2(a4), r5 = unpack2(a5), r6 = unpack2(a6), r7 = unpack2(a7);
        float2 o1 = make_float2(0.5f * (r4.x + r4.y + r5.x + r5.y) + b2p.x,
                                0.5f * (r6.x + r6.y + r7.x + r7.y) + b2p.y);
        ((float2*)(out + (size_t)(2 * pi + 1) * DIM))[lane] = o1;

        __syncwarp();
        pi = pn;
    }
}

extern "C" void kernel_launch(void* const* d_in, const int* in_sizes, int n_in,
                              void* d_out, int out_size) {
    const float4* edge_feat = (const float4*)d_in[0];
    const void*   src       = d_in[1];
    const void*   dst       = d_in[2];
    const float*  W1        = (const float*)d_in[3];
    const float*  b1        = (const float*)d_in[4];
    const float*  W2        = (const float*)d_in[5];
    const float*  b2        = (const float*)d_in[6];
    float*        out       = (float*)d_out;

    detect_kernel<<<1, 32>>>((const int*)src);
    zero_kernel<<<(NNODES * DIM / 4 + 255) / 256, 256>>>();
    scatter_kernel<<<(NEDGES * 16 + 255) / 256, 256>>>(edge_feat, dst);
    node_mm_kernel<<<2048, 128>>>(W1, b1);
    edge_kernel<<<4096, 128>>>(src, dst, W2, b2, out);
}

// round 7
// speedup vs baseline: 3.2040x; 2.2882x over previous
#include <cuda_runtime.h>
#include <cuda_bf16.h>
#include <cstdint>
#include <cstddef>

#define NNODES 50000
#define NEDGES 800000
#define DIM 64
#define ETILES (NEDGES / 16)    // 50000
#define NTILES (NNODES / 16)    // 3125

__device__ float g_node_x[NNODES * DIM];
__device__ float g_y[NNODES * DIM];      // node_x @ W1 + 0.5*b1
__device__ int   g_is64;

// pack two fp32 -> bf16x2 (bits[15:0]=lo elem, bits[31:16]=hi elem)
__device__ __forceinline__ uint32_t bf2(float lo, float hi) {
    uint32_t r;
    asm("cvt.rn.bf16x2.f32 %0, %1, %2;" : "=r"(r) : "f"(hi), "f"(lo));
    return r;
}
// residual split: lo-part of (x,y) given their packed bf16 hi approximation
__device__ __forceinline__ uint32_t bf2lo(uint32_t h, float x, float y) {
    return bf2(x - __uint_as_float(h << 16), y - __uint_as_float(h & 0xFFFF0000u));
}
__device__ __forceinline__ void mma_bf16(float* d, const uint32_t* a, const uint32_t* b) {
    asm volatile(
        "mma.sync.aligned.m16n8k16.row.col.f32.bf16.bf16.f32 "
        "{%0,%1,%2,%3}, {%4,%5,%6,%7}, {%8,%9}, {%0,%1,%2,%3};"
        : "+f"(d[0]), "+f"(d[1]), "+f"(d[2]), "+f"(d[3])
        : "r"(a[0]), "r"(a[1]), "r"(a[2]), "r"(a[3]), "r"(b[0]), "r"(b[1]));
}

// ---------------- small kernels ----------------
__global__ void detect_kernel(const int* __restrict__ src) {
    if (threadIdx.x == 0) {
        int z = 1;
        #pragma unroll
        for (int i = 0; i < 32; i++) z &= (src[2 * i + 1] == 0);
        g_is64 = z;
    }
}

__global__ void zero_kernel() {
    int i = blockIdx.x * blockDim.x + threadIdx.x;
    float4* p = (float4*)g_node_x;
    if (i < NNODES * DIM / 4) p[i] = make_float4(0.f, 0.f, 0.f, 0.f);
}

__global__ void scatter_kernel(const float4* __restrict__ ef, const void* __restrict__ dstp) {
    int t = blockIdx.x * blockDim.x + threadIdx.x;
    if (t >= NEDGES * (DIM / 4)) return;
    int e = t >> 4;
    int q = t & 15;
    long long d = g_is64 ? ((const long long*)dstp)[e]
                         : (long long)((const int*)dstp)[e];
    float4 v = ef[t];
    float* addr = g_node_x + d * DIM + q * 4;
    asm volatile("red.global.add.v4.f32 [%0], {%1, %2, %3, %4};"
                 :: "l"(addr), "f"(v.x), "f"(v.y), "f"(v.z), "f"(v.w) : "memory");
}

// ---------------- HMMA MLP kernel ----------------
// EDGE=false: y[row]   = node_x[row] @ W1 + 0.5*b1
// EDGE=true : out[row] = 0.5*(relu(y[src]+y[dst]) @ W2) + 0.5*b2
// One warp per 16-row tile. B = W^T (hi/lo bf16 split) in registers, loaded once.
template <bool EDGE>
__global__ void __launch_bounds__(256, 1) mlp_kernel(
    const void* __restrict__ srcp, const void* __restrict__ dstp,
    const float* __restrict__ W, const float* __restrict__ bias,
    float* __restrict__ outp, int ntiles)
{
    const int tid = threadIdx.x;
    const int warp = tid >> 5, lane = tid & 31;
    const int g = lane >> 2, tg = lane & 3;
    const int is64 = EDGE ? g_is64 : 0;
    const float* __restrict__ Abase = EDGE ? g_y : g_node_x;
    float* __restrict__ out = EDGE ? outp : g_y;
    constexpr float SC = EDGE ? 0.5f : 1.0f;

    // B fragments: Bhi/Blo[nt][ks][khalf]; B[k][n] = W[k][n] (mma .col wants (k,n) per map)
    uint32_t Bhi[8][4][2], Blo[8][4][2];
    #pragma unroll
    for (int nt = 0; nt < 8; nt++) {
        int n = nt * 8 + g;
        #pragma unroll
        for (int ks = 0; ks < 4; ks++) {
            #pragma unroll
            for (int hx = 0; hx < 2; hx++) {
                int k = ks * 16 + 2 * tg + 8 * hx;
                float w0 = W[k * DIM + n];
                float w1 = W[(k + 1) * DIM + n];
                uint32_t h = bf2(w0, w1);
                Bhi[nt][ks][hx] = h;
                Blo[nt][ks][hx] = bf2lo(h, w0, w1);
            }
        }
    }

    const int gw = blockIdx.x * 8 + warp;
    const int nw = gridDim.x * 8;
    for (int tile = gw; tile < ntiles; tile += nw) {
        const int r0 = tile * 16 + g;     // this thread's two rows
        const int r1 = r0 + 8;

        const float *p0a, *p0b = nullptr, *p1a, *p1b = nullptr;
        if (EDGE) {
            long long s0, d0, s1, d1;
            if (is64) {
                s0 = ((const long long*)srcp)[r0]; d0 = ((const long long*)dstp)[r0];
                s1 = ((const long long*)srcp)[r1]; d1 = ((const long long*)dstp)[r1];
            } else {
                s0 = ((const int*)srcp)[r0]; d0 = ((const int*)dstp)[r0];
                s1 = ((const int*)srcp)[r1]; d1 = ((const int*)dstp)[r1];
            }
            p0a = Abase + s0 * DIM; p0b = Abase + d0 * DIM;
            p1a = Abase + s1 * DIM; p1b = Abase + d1 * DIM;
        } else {
            p0a = Abase + (long long)r0 * DIM;
            p1a = Abase + (long long)r1 * DIM;
        }

        float acc[8][4];
        #pragma unroll
        for (int nt = 0; nt < 8; nt++) {
            acc[nt][0] = 0.f; acc[nt][1] = 0.f; acc[nt][2] = 0.f; acc[nt][3] = 0.f;
        }

        #pragma unroll
        for (int ks = 0; ks < 4; ks++) {
            const int c0 = ks * 16 + 2 * tg;     // k columns c0,c0+1 and c0+8,c0+9
            float2 h00, h01, h10, h11;
            if (EDGE) {
                float2 a, b;
                a = *(const float2*)(p0a + c0);     b = *(const float2*)(p0b + c0);
                h00 = make_float2(fmaxf(a.x + b.x, 0.f), fmaxf(a.y + b.y, 0.f));
                a = *(const float2*)(p0a + c0 + 8); b = *(const float2*)(p0b + c0 + 8);
                h01 = make_float2(fmaxf(a.x + b.x, 0.f), fmaxf(a.y + b.y, 0.f));
                a = *(const float2*)(p1a + c0);     b = *(const float2*)(p1b + c0);
                h10 = make_float2(fmaxf(a.x + b.x, 0.f), fmaxf(a.y + b.y, 0.f));
                a = *(const float2*)(p1a + c0 + 8); b = *(const float2*)(p1b + c0 + 8);
                h11 = make_float2(fmaxf(a.x + b.x, 0.f), fmaxf(a.y + b.y, 0.f));
            } else {
                h00 = *(const float2*)(p0a + c0);
                h01 = *(const float2*)(p0a + c0 + 8);
                h10 = *(const float2*)(p1a + c0);
                h11 = *(const float2*)(p1a + c0 + 8);
            }
            uint32_t ahi[4], alo[4];
            ahi[0] = bf2(h00.x, h00.y);  alo[0] = bf2lo(ahi[0], h00.x, h00.y);
            ahi[1] = bf2(h10.x, h10.y);  alo[1] = bf2lo(ahi[1], h10.x, h10.y);
            ahi[2] = bf2(h01.x, h01.y);  alo[2] = bf2lo(ahi[2], h01.x, h01.y);
            ahi[3] = bf2(h11.x, h11.y);  alo[3] = bf2lo(ahi[3], h11.x, h11.y);

            #pragma unroll
            for (int nt = 0; nt < 8; nt++) {
                mma_bf16(acc[nt], ahi, Bhi[nt][ks]);
                mma_bf16(acc[nt], alo, Bhi[nt][ks]);
                mma_bf16(acc[nt], ahi, Blo[nt][ks]);
            }
        }

        // epilogue: d0,d1 -> row r0 cols (nt*8+2tg, +1); d2,d3 -> row r1
        float* o0 = out + (long long)r0 * DIM;
        float* o1 = out + (long long)r1 * DIM;
        #pragma unroll
        for (int nt = 0; nt < 8; nt++) {
            float2 bb = *(const float2*)(bias + nt * 8 + 2 * tg);
            float2 v0 = make_float2(SC * acc[nt][0] + 0.5f * bb.x,
                                    SC * acc[nt][1] + 0.5f * bb.y);
            float2 v1 = make_float2(SC * acc[nt][2] + 0.5f * bb.x,
                                    SC * acc[nt][3] + 0.5f * bb.y);
            *(float2*)(o0 + nt * 8 + 2 * tg) = v0;
            *(float2*)(o1 + nt * 8 + 2 * tg) = v1;
        }
    }
}

// ---------------- launch ----------------
extern "C" void kernel_launch(void* const* d_in, const int* in_sizes, int n_in,
                              void* d_out, int out_size) {
    const float4* edge_feat = (const float4*)d_in[0];
    const void*   src       = d_in[1];
    const void*   dst       = d_in[2];
    const float*  W1        = (const float*)d_in[3];
    const float*  b1        = (const float*)d_in[4];
    const float*  W2        = (const float*)d_in[5];
    const float*  b2        = (const float*)d_in[6];
    float*        out       = (float*)d_out;

    detect_kernel<<<1, 32>>>((const int*)src);
    zero_kernel<<<(NNODES * DIM / 4 + 255) / 256, 256>>>();
    scatter_kernel<<<(NEDGES * 16 + 255) / 256, 256>>>(edge_feat, dst);
    mlp_kernel<false><<<148, 256>>>(nullptr, nullptr, W1, b1, nullptr, NTILES);
    mlp_kernel<true><<<148, 256>>>(src, dst, W2, b2, out, ETILES);
}